// round 17
// baseline (speedup 1.0000x reference)
#include <cuda_runtime.h>
#include <cuda_bf16.h>
#include <math.h>
#include <stdint.h>

#define EDIM 1024
#define NH   16
#define HD   64
#define TQ   2048
#define NB   4
#define MROWS (NB*TQ)   // 8192

#if defined(__CUDA_ARCH_FEAT_SM103_ALL) || defined(__CUDA_ARCH_FEAT_SM100_ALL) || \
    defined(__CUDA_ARCH_FEAT_SM101_ALL) || defined(__CUDA_ARCH_SPECIFIC__)
#define TCGEN05_OK 1
#endif

// ---------------- scratch (device globals: no allocations allowed) ----------
__device__ float g_q [MROWS*EDIM];
__device__ float g_k [MROWS*EDIM];
__device__ __nv_bfloat16 g_xhi [MROWS*EDIM];
__device__ __nv_bfloat16 g_xlo [MROWS*EDIM];
__device__ __nv_bfloat16 g_qhi [MROWS*EDIM];
__device__ __nv_bfloat16 g_qlo [MROWS*EDIM];
__device__ __nv_bfloat16 g_khi [MROWS*EDIM];
__device__ __nv_bfloat16 g_klo [MROWS*EDIM];
__device__ __nv_bfloat16 g_vthi[MROWS*EDIM];   // V^T per (b,h): [64 d][2048 tok]
__device__ __nv_bfloat16 g_vtlo[MROWS*EDIM];
__device__ __nv_bfloat16 g_aohi[MROWS*EDIM];
__device__ __nv_bfloat16 g_aolo[MROWS*EDIM];
__device__ __nv_bfloat16 g_wthi[4*EDIM*EDIM];   // W^T (N-major rows, K contiguous)
__device__ __nv_bfloat16 g_wtlo[4*EDIM*EDIM];

// ======================= PTX helpers (sm_103a) ==============================
__device__ __forceinline__ uint32_t smem_to_u32(const void* p) {
    uint32_t a;
    asm("{ .reg .u64 t; cvta.to.shared.u64 t, %1; cvt.u32.u64 %0, t; }" : "=r"(a) : "l"(p));
    return a;
}
__device__ __forceinline__ uint32_t elect_one_pred() {
    uint32_t pred;
    asm volatile("{\n\t.reg .pred p;\n\telect.sync _|p, 0xFFFFFFFF;\n\tselp.b32 %0, 1, 0, p;\n\t}" : "=r"(pred));
    return pred;
}
#define MBARRIER_INIT(mbar, count) \
    asm volatile("mbarrier.init.shared.b64 [%0], %1;" :: "r"((uint32_t)(mbar)), "r"((uint32_t)(count)) : "memory")
#define MBARRIER_WAIT_PARITY(mbar_smem_addr, phase_parity) do { \
    uint32_t _mbar = (uint32_t)(mbar_smem_addr); \
    uint32_t _parity = (uint32_t)(phase_parity); \
    uint32_t _done; \
    asm volatile("{\n\t.reg .pred p;\n\tmbarrier.try_wait.parity.acquire.cta.shared::cta.b64 p, [%1], %2;\n\tselp.b32 %0, 1, 0, p;\n\t}" \
        : "=r"(_done) : "r"(_mbar), "r"(_parity) : "memory"); \
    if (!_done) { \
        asm volatile("{\n\t.reg .pred P1;\n\tWAIT_LOOP_%=:\n\t" \
            "mbarrier.try_wait.parity.acquire.cta.shared::cta.b64 P1, [%0], %1, 0x989680;\n\t" \
            "@P1 bra.uni WAIT_DONE_%=;\n\tbra.uni WAIT_LOOP_%=;\n\tWAIT_DONE_%=:\n\t}" \
            :: "r"(_mbar), "r"(_parity) : "memory"); \
    } \
} while(0)

#define CP_ASYNC16(dst, src) \
    asm volatile("cp.async.cg.shared.global [%0], [%1], 16;" :: "r"((uint32_t)(dst)), "l"(src) : "memory")
#define CP_COMMIT() asm volatile("cp.async.commit_group;" ::: "memory")
#define CP_WAIT0()  asm volatile("cp.async.wait_group 0;" ::: "memory")
#define CP_WAIT1()  asm volatile("cp.async.wait_group 1;" ::: "memory")

#ifdef TCGEN05_OK
#define TCGEN05_ALLOC(smem_addr, nCols) \
    asm volatile("tcgen05.alloc.cta_group::1.sync.aligned.shared::cta.b32 [%0], %1;" \
        :: "r"((uint32_t)(smem_addr)), "r"((uint32_t)(nCols)) : "memory")
#define TCGEN05_DEALLOC(tmem_addr, nCols) \
    asm volatile("tcgen05.dealloc.cta_group::1.sync.aligned.b32 %0, %1;" :: "r"(tmem_addr), "r"((uint32_t)(nCols)))
#define TCGEN05_RELINQUISH() \
    asm volatile("tcgen05.relinquish_alloc_permit.cta_group::1.sync.aligned;")
#define TCGEN05_COMMIT(mbar) \
    asm volatile("tcgen05.commit.cta_group::1.mbarrier::arrive::one.shared::cluster.b64 [%0];" \
        :: "r"((uint32_t)(mbar)) : "memory")
#define TCGEN05_FENCE_BEFORE() asm volatile("tcgen05.fence::before_thread_sync;" ::: "memory")
#define TCGEN05_FENCE_AFTER()  asm volatile("tcgen05.fence::after_thread_sync;" ::: "memory")
#define TCGEN05_WAIT_LD()      asm volatile("tcgen05.wait::ld.sync.aligned;" ::: "memory")
#define TCGEN05_WAIT_ST()      asm volatile("tcgen05.wait::st.sync.aligned;" ::: "memory")

#define TCGEN05_LD_32X32B_X32(r, tmem_addr) \
    asm volatile("tcgen05.ld.sync.aligned.32x32b.x32.b32 " \
        "{%0, %1, %2, %3, %4, %5, %6, %7, %8, %9, %10, %11, %12, %13, %14, %15, " \
        " %16, %17, %18, %19, %20, %21, %22, %23, %24, %25, %26, %27, %28, %29, %30, %31}, [%32];" \
        : "=r"((r)[0]),  "=r"((r)[1]),  "=r"((r)[2]),  "=r"((r)[3]), \
          "=r"((r)[4]),  "=r"((r)[5]),  "=r"((r)[6]),  "=r"((r)[7]), \
          "=r"((r)[8]),  "=r"((r)[9]),  "=r"((r)[10]), "=r"((r)[11]), \
          "=r"((r)[12]), "=r"((r)[13]), "=r"((r)[14]), "=r"((r)[15]), \
          "=r"((r)[16]), "=r"((r)[17]), "=r"((r)[18]), "=r"((r)[19]), \
          "=r"((r)[20]), "=r"((r)[21]), "=r"((r)[22]), "=r"((r)[23]), \
          "=r"((r)[24]), "=r"((r)[25]), "=r"((r)[26]), "=r"((r)[27]), \
          "=r"((r)[28]), "=r"((r)[29]), "=r"((r)[30]), "=r"((r)[31]) \
        : "r"(tmem_addr))

#define TCGEN05_ST_32X32B_X16(tmem_addr, r) \
    asm volatile("tcgen05.st.sync.aligned.32x32b.x16.b32 [%0], " \
        "{%1, %2, %3, %4, %5, %6, %7, %8, %9, %10, %11, %12, %13, %14, %15, %16};" \
        :: "r"(tmem_addr), \
           "r"((r)[0]),  "r"((r)[1]),  "r"((r)[2]),  "r"((r)[3]), \
           "r"((r)[4]),  "r"((r)[5]),  "r"((r)[6]),  "r"((r)[7]), \
           "r"((r)[8]),  "r"((r)[9]),  "r"((r)[10]), "r"((r)[11]), \
           "r"((r)[12]), "r"((r)[13]), "r"((r)[14]), "r"((r)[15]) \
        : "memory")

__device__ __forceinline__ void mma_f16_ss_cg1(uint32_t d, uint64_t a, uint64_t b,
                                               uint32_t idesc, uint32_t en) {
    asm volatile(
        "{\n\t.reg .pred p;\n\tsetp.ne.u32 p, %5, 0;\n\t"
        "tcgen05.mma.cta_group::1.kind::f16 [%0], %1, %2, %3, {%4,%4,%4,%4}, p;\n\t}"
        :: "r"(d), "l"(a), "l"(b), "r"(idesc), "r"(0u), "r"(en) : "memory");
}
__device__ __forceinline__ void mma_f16_ts_cg1(uint32_t d, uint32_t a_tmem, uint64_t b,
                                               uint32_t idesc, uint32_t en) {
    asm volatile(
        "{\n\t.reg .pred p;\n\tsetp.ne.u32 p, %5, 0;\n\t"
        "tcgen05.mma.cta_group::1.kind::f16 [%0], [%1], %2, %3, {%4,%4,%4,%4}, p;\n\t}"
        :: "r"(d), "r"(a_tmem), "l"(b), "r"(idesc), "r"(0u), "r"(en) : "memory");
}
#endif // TCGEN05_OK

// K-major SW128 descriptor (LBO=1, SBO=64)
static constexpr uint64_t SMEM_DESC_BASE_SW128 =
    (uint64_t(2)  << 61) | (uint64_t(1) << 46) | (uint64_t(64) << 32) | (uint64_t(1) << 16);
#define MAKE_SMEM_DESC(base_addr) (SMEM_DESC_BASE_SW128 | ((uint64_t)((base_addr) >> 4) & 0x3FFF))

#define IDESC_S  0x8200490u
#define IDESC_PV 0x8100490u

// ======================= tcgen05 GEMM v2 (cp.async, 128x256 tile) ===========
#define G2_STAGE_BYTES 98304
#define G2_HDR 1024
#define GEMM_SMEM (G2_HDR + 2*G2_STAGE_BYTES)   // 197632

__device__ __forceinline__ void gemm_cp_stage(
    uint32_t sdst, const __nv_bfloat16* Ahi, const __nv_bfloat16* Alo,
    const __nv_bfloat16* Bhi, const __nv_bfloat16* Blo,
    int bm, int bnw, int c, int tid)
{
#pragma unroll
    for (int j = 0; j < 2; j++) {
        const int i = j * 512 + tid;
        const int r = i >> 3, g = i & 7;
        uint32_t off = (uint32_t)(r * 128 + g * 16);
        off ^= (off >> 3) & 0x70;
        const size_t go = (((size_t)(bm + r)) << 10) + c * 64 + g * 8;
        CP_ASYNC16(sdst + off,         Ahi + go);
        CP_ASYNC16(sdst + 16384 + off, Alo + go);
    }
#pragma unroll
    for (int j = 0; j < 4; j++) {
        const int i = j * 512 + tid;
        const int r = i >> 3, g = i & 7;
        uint32_t off = (uint32_t)(r * 128 + g * 16);
        off ^= (off >> 3) & 0x70;
        const size_t go = (((size_t)(bnw + r)) << 10) + c * 64 + g * 8;
        CP_ASYNC16(sdst + 32768 + off, Bhi + go);
        CP_ASYNC16(sdst + 65536 + off, Blo + go);
    }
}

__global__ __launch_bounds__(512, 1)
void gemm_tc2_kernel(const __nv_bfloat16* __restrict__ Ahi,
                     const __nv_bfloat16* __restrict__ Alo,
                     const __nv_bfloat16* __restrict__ WThi,
                     const __nv_bfloat16* __restrict__ WTlo,
                     int wbase,
                     const float* __restrict__ b0,
                     const float* __restrict__ b1,
                     const float* __restrict__ b2,
                     float* __restrict__ C0,
                     float* __restrict__ C1,
                     __nv_bfloat16* __restrict__ Vthi,
                     __nv_bfloat16* __restrict__ Vtlo,
                     int vz)
{
#ifdef TCGEN05_OK
    extern __shared__ char smem[];
    const uint32_t sbase = smem_to_u32(smem);
    const int tid = threadIdx.x;
    const int wid = tid >> 5;
    const int lid = tid & 31;
    const int bm = blockIdx.y * 128;
    const int bn = blockIdx.x * 256;
    const int z  = blockIdx.z;
    const int w  = wbase + z;
    const float* bias = (z == 0) ? b0 : (z == 1) ? b1 : b2;
    float* Cout = (z == 0) ? C0 : C1;
    const bool vmode = (z == vz);
    const int bnw = w * 1024 + bn;

    if (wid == 0) TCGEN05_ALLOC(sbase + 0, 256);
    if (tid == 0) {
        MBARRIER_INIT(sbase + 16, 1);
        MBARRIER_INIT(sbase + 24, 1);
        MBARRIER_INIT(sbase + 32, 1);
    }
    __syncthreads();
    uint32_t tmem;
    asm volatile("ld.shared.b32 %0, [%1];" : "=r"(tmem) : "r"(sbase + 0));

    gemm_cp_stage(sbase + G2_HDR, Ahi, Alo, WThi, WTlo, bm, bnw, 0, tid);
    CP_COMMIT();

    int phD0 = 0, phD1 = 0;
    for (int c = 0; c < 16; c++) {
        if (c + 1 < 16) {
            const int b2s = (c + 1) & 1;
            if (c + 1 >= 2) {
                if (b2s == 0) { MBARRIER_WAIT_PARITY(sbase + 16, phD0); phD0 ^= 1; }
                else          { MBARRIER_WAIT_PARITY(sbase + 24, phD1); phD1 ^= 1; }
            }
            gemm_cp_stage(sbase + G2_HDR + b2s * G2_STAGE_BYTES,
                          Ahi, Alo, WThi, WTlo, bm, bnw, c + 1, tid);
            CP_COMMIT();
            CP_WAIT1();
        } else {
            CP_WAIT0();
        }
        __syncthreads();

        if (wid == 0) {
            TCGEN05_FENCE_AFTER();
            if (elect_one_pred()) {
                asm volatile("fence.proxy.async.shared::cta;" ::: "memory");
                const uint32_t stg = sbase + G2_HDR + (c & 1) * G2_STAGE_BYTES;
                const uint64_t dAh = MAKE_SMEM_DESC(stg + 0);
                const uint64_t dAl = MAKE_SMEM_DESC(stg + 16384);
                const uint64_t dBh = MAKE_SMEM_DESC(stg + 32768);
                const uint64_t dBl = MAKE_SMEM_DESC(stg + 65536);
#pragma unroll
                for (int k = 0; k < 4; k++) {
#pragma unroll
                    for (int hf = 0; hf < 2; hf++) {
                        const uint64_t hb = (uint64_t)(hf * 1024);
                        const uint32_t dd = tmem + hf * 128;
                        mma_f16_ss_cg1(dd, dAh + 2*k, dBh + 2*k + hb, IDESC_S, (c > 0 || k > 0));
                        mma_f16_ss_cg1(dd, dAh + 2*k, dBl + 2*k + hb, IDESC_S, 1);
                        mma_f16_ss_cg1(dd, dAl + 2*k, dBh + 2*k + hb, IDESC_S, 1);
                    }
                }
                TCGEN05_COMMIT(sbase + 16 + 8 * (c & 1));
            }
        }
    }

    if (wid == 0) {
        if (elect_one_pred()) TCGEN05_COMMIT(sbase + 32);
    }
    MBARRIER_WAIT_PARITY(sbase + 32, 0);
    TCGEN05_FENCE_AFTER();

    {
        const int subp = wid & 3;
        const int colq = wid >> 2;
        const int row  = bm + subp * 32 + lid;
        const uint32_t woff = (uint32_t)subp << 21;
        uint32_t d0[32], d1[32];
        TCGEN05_LD_32X32B_X32(d0, tmem + woff + colq * 64);
        TCGEN05_LD_32X32B_X32(d1, tmem + woff + colq * 64 + 32);
        TCGEN05_WAIT_LD();
        if (!vmode) {
            float* cp = Cout + (size_t)row * EDIM + bn + colq * 64;
            const float* bp = bias + bn + colq * 64;
#pragma unroll
            for (int c4 = 0; c4 < 8; c4++) {
                float4 o;
                o.x = __uint_as_float(d0[c4*4+0]) + bp[c4*4+0];
                o.y = __uint_as_float(d0[c4*4+1]) + bp[c4*4+1];
                o.z = __uint_as_float(d0[c4*4+2]) + bp[c4*4+2];
                o.w = __uint_as_float(d0[c4*4+3]) + bp[c4*4+3];
                *reinterpret_cast<float4*>(cp + c4*4) = o;
            }
#pragma unroll
            for (int c4 = 0; c4 < 8; c4++) {
                float4 o;
                o.x = __uint_as_float(d1[c4*4+0]) + bp[32 + c4*4+0];
                o.y = __uint_as_float(d1[c4*4+1]) + bp[32 + c4*4+1];
                o.z = __uint_as_float(d1[c4*4+2]) + bp[32 + c4*4+2];
                o.w = __uint_as_float(d1[c4*4+3]) + bp[32 + c4*4+3];
                *reinterpret_cast<float4*>(cp + 32 + c4*4) = o;
            }
        } else {
            const int bb  = row >> 11;
            const int tok = row & (TQ - 1);
#pragma unroll
            for (int j = 0; j < 64; j++) {
                const int colg = bn + colq * 64 + j;
                const float f = __uint_as_float(j < 32 ? d0[j] : d1[j - 32]) + bias[colg];
                const __nv_bfloat16 hh = __float2bfloat16_rn(f);
                const __nv_bfloat16 ll = __float2bfloat16_rn(f - __bfloat162float(hh));
                const size_t dst = ((size_t)((bb * NH + (colg >> 6)) * HD + (colg & 63))) * TQ + tok;
                Vthi[dst] = hh;
                Vtlo[dst] = ll;
            }
        }
    }
    __syncthreads();
    if (wid == 0) {
        TCGEN05_RELINQUISH();
        TCGEN05_DEALLOC(tmem, 256);
    }
#endif
}

// ======================= tensor-core flash attention v5 =====================
// 512 threads (16 warps): warp = (subp, quarter). Each thread owns one q-row
// and 32 S-columns — softmax ALU work per tile halved vs the 256-thread v4.
#define AT_THREADS 512
#define AT_LPART 1024                      // 128 rows x 4 partials x 4B = 2KB
#define AT_QHI   3072
#define AT_QLO   (AT_QHI + 16384)          // 19456
#define AT_K0    (AT_QLO + 16384)          // 35840 ; 2 slots x 32KB
#define AT_V0    (AT_K0 + 2*32768)         // 101376 ; 3 slots x 32KB
#define AT_SMEM_TOTAL (AT_V0 + 3*32768)    // 199680

__device__ __forceinline__ void at_cp_tile(const __nv_bfloat16* g, int tok0, int colb,
                                           uint32_t sdst, int tid)
{
#pragma unroll
    for (int j = 0; j < 2; j++) {
        const int i = j * 512 + tid;
        const int r = i >> 3, c8 = i & 7;
        uint32_t off = (uint32_t)(r * 128 + c8 * 16);
        off ^= (off >> 3) & 0x70;
        CP_ASYNC16(sdst + off, g + (((size_t)(tok0 + r)) << 10) + colb + c8 * 8);
    }
}

__device__ __forceinline__ void at_cp_vt(const __nv_bfloat16* vt, int bh, int kb,
                                         uint32_t sdst, int tid)
{
#pragma unroll
    for (int j = 0; j < 2; j++) {
        const int i = j * 512 + tid;
        const int r = i >> 4, c16 = i & 15;
        uint32_t off = (uint32_t)((r >> 3) * 1024 + (c16 >> 3) * 8192 + (r & 7) * 128 + (c16 & 7) * 16);
        off ^= (off >> 3) & 0x70;
        CP_ASYNC16(sdst + off, vt + ((size_t)(bh * HD + r)) * TQ + kb + c16 * 8);
    }
}

__global__ __launch_bounds__(AT_THREADS, 1)
void attention_tc_kernel(const __nv_bfloat16* __restrict__ Qhi_g,
                         const __nv_bfloat16* __restrict__ Qlo_g,
                         const __nv_bfloat16* __restrict__ Khi_g,
                         const __nv_bfloat16* __restrict__ Klo_g,
                         const __nv_bfloat16* __restrict__ Vthi_g,
                         const __nv_bfloat16* __restrict__ Vtlo_g,
                         __nv_bfloat16* __restrict__ Ohi_g,
                         __nv_bfloat16* __restrict__ Olo_g)
{
#ifdef TCGEN05_OK
    extern __shared__ char smem[];
    const uint32_t sbase = smem_to_u32(smem);
    const int tid = threadIdx.x;
    const int wid = tid >> 5;
    const int lid = tid & 31;
    const int b = blockIdx.z, h = blockIdx.y;
    const int bh = b * NH + h;
    const int tok0 = b * TQ + blockIdx.x * 128;
    const int colb = h * HD;
    const uint32_t mbarS = sbase + 16, mbarO = sbase + 24;

    if (wid == 0) TCGEN05_ALLOC(sbase + 0, 512);
    if (tid == 0) { MBARRIER_INIT(mbarS, 1); MBARRIER_INIT(mbarO, 1); }
    __syncthreads();
    uint32_t tmem;
    asm volatile("ld.shared.b32 %0, [%1];" : "=r"(tmem) : "r"(sbase + 0));

    at_cp_tile(Qhi_g, tok0, colb, sbase + AT_QHI, tid);
    at_cp_tile(Qlo_g, tok0, colb, sbase + AT_QLO, tid);
    at_cp_tile(Khi_g, b * TQ, colb, sbase + AT_K0, tid);
    at_cp_tile(Klo_g, b * TQ, colb, sbase + AT_K0 + 16384, tid);
    at_cp_vt(Vthi_g, bh, 0, sbase + AT_V0, tid);
    at_cp_vt(Vtlo_g, bh, 0, sbase + AT_V0 + 16384, tid);
    CP_COMMIT();
    CP_WAIT0();
    __syncthreads();

    const uint64_t dQh = MAKE_SMEM_DESC(sbase + AT_QHI);
    const uint64_t dQl = MAKE_SMEM_DESC(sbase + AT_QLO);

    // issue S(0)
    if (wid == 0) {
        TCGEN05_FENCE_AFTER();
        if (elect_one_pred()) {
            asm volatile("fence.proxy.async.shared::cta;" ::: "memory");
            const uint64_t dKh = MAKE_SMEM_DESC(sbase + AT_K0);
            const uint64_t dKl = MAKE_SMEM_DESC(sbase + AT_K0 + 16384);
#pragma unroll
            for (int k = 0; k < 4; k++) {
                mma_f16_ss_cg1(tmem + 0, dQh + 2*k, dKh + 2*k, IDESC_S, (k > 0));
                mma_f16_ss_cg1(tmem + 0, dQh + 2*k, dKl + 2*k, IDESC_S, 1);
                mma_f16_ss_cg1(tmem + 0, dQl + 2*k, dKh + 2*k, IDESC_S, 1);
            }
            TCGEN05_COMMIT(mbarS);
        }
    }

    const int subp = wid & 3;
    const int quarter = wid >> 2;        // 0..3 : S-column quarter
    const int qrow = subp * 32 + lid;
    const uint32_t loff = (uint32_t)subp << 21;
    float l_part = 0.0f;
    const float CEX = 0.125f * 1.44269504f;

    for (int t = 0; t < 16; t++) {
        // fire loads(t+1): separate K and V commit groups
        if (t + 1 < 16) {
            const int kb = (t + 1) * 128;
            const uint32_t ks = sbase + AT_K0 + ((t + 1) & 1) * 32768;
            const uint32_t vs = sbase + AT_V0 + ((t + 1) % 3) * 32768;
            at_cp_tile(Khi_g, b * TQ + kb, colb, ks, tid);
            at_cp_tile(Klo_g, b * TQ + kb, colb, ks + 16384, tid);
            CP_COMMIT();                         // group: K(t+1)
            at_cp_vt(Vthi_g, bh, kb, vs, tid);
            at_cp_vt(Vtlo_g, bh, kb, vs + 16384, tid);
            CP_COMMIT();                         // group: V(t+1)
        }

        // wait S(t), softmax on this thread's 32 columns
        MBARRIER_WAIT_PARITY(mbarS, t & 1);
        TCGEN05_FENCE_AFTER();

        uint32_t hiw[16], low[16];
        {
            const uint32_t sb = tmem + (t & 1) * 128 + quarter * 32 + loff;
            uint32_t r0[32];
            TCGEN05_LD_32X32B_X32(r0, sb);
            TCGEN05_WAIT_LD();
            float p[32];
            float psum = 0.0f;
#pragma unroll
            for (int j = 0; j < 32; j++) {
                float a0 = __uint_as_float(r0[j]) * CEX;
                float e0;
                asm("ex2.approx.f32 %0, %1;" : "=f"(e0) : "f"(a0));
                p[j] = e0;
                psum += e0;
            }
            l_part += psum;
#pragma unroll
            for (int j2 = 0; j2 < 16; j2++) {
                float p0 = p[2*j2], p1 = p[2*j2 + 1];
                uint32_t wh;
                asm("cvt.rn.bf16x2.f32 %0, %1, %2;" : "=r"(wh) : "f"(p1), "f"(p0));
                float h0 = __uint_as_float(wh << 16);
                float h1 = __uint_as_float(wh & 0xffff0000u);
                float q0 = p0 - h0, q1 = p1 - h1;
                uint32_t wl;
                asm("cvt.rn.bf16x2.f32 %0, %1, %2;" : "=r"(wl) : "f"(q1), "f"(q0));
                hiw[j2] = wh; low[j2] = wl;
            }
        }

        // K(t+1) ready (V(t+1) may still fly); also guarantees V(t) resident.
        if (t + 1 < 16) CP_WAIT1(); else CP_WAIT0();
        __syncthreads();

        // issue S(t+1) EARLY — overlaps mbarO wait + STTM + PV issue
        if (t + 1 < 16 && wid == 0) {
            if (elect_one_pred()) {
                asm volatile("fence.proxy.async.shared::cta;" ::: "memory");
                const uint32_t ks = sbase + AT_K0 + ((t + 1) & 1) * 32768;
                const uint64_t dKh = MAKE_SMEM_DESC(ks);
                const uint64_t dKl = MAKE_SMEM_DESC(ks + 16384);
                const uint32_t sdst = tmem + ((t + 1) & 1) * 128;
#pragma unroll
                for (int k = 0; k < 4; k++) {
                    mma_f16_ss_cg1(sdst, dQh + 2*k, dKh + 2*k, IDESC_S, (k > 0));
                    mma_f16_ss_cg1(sdst, dQh + 2*k, dKl + 2*k, IDESC_S, 1);
                    mma_f16_ss_cg1(sdst, dQl + 2*k, dKh + 2*k, IDESC_S, 1);
                }
                TCGEN05_COMMIT(mbarS);
            }
        }

        // P TMEM single-buffered: PV(t-1) must be done before overwrite
        if (t >= 1) { MBARRIER_WAIT_PARITY(mbarO, (t - 1) & 1); TCGEN05_FENCE_AFTER(); }

        // STTM P hi/lo: warp (subp,quarter) writes bf16x2 cols quarter*16..+16
        TCGEN05_ST_32X32B_X16(tmem + 320 + quarter * 16 + loff, hiw);
        TCGEN05_ST_32X32B_X16(tmem + 384 + quarter * 16 + loff, low);
        TCGEN05_WAIT_ST();
        TCGEN05_FENCE_BEFORE();
        __syncthreads();

        // PV(t): TS-mode, A = P in TMEM, B = V^T K-major
        if (wid == 0) {
            TCGEN05_FENCE_AFTER();
            if (elect_one_pred()) {
                asm volatile("fence.proxy.async.shared::cta;" ::: "memory");
                const uint32_t vs = sbase + AT_V0 + (t % 3) * 32768;
                const uint64_t dVh = MAKE_SMEM_DESC(vs);
                const uint64_t dVl = MAKE_SMEM_DESC(vs + 16384);
#pragma unroll
                for (int s = 0; s < 8; s++) {
                    const uint64_t vb = (uint64_t)((s & 3) * 2 + (s >> 2) * 512);
                    const uint32_t pah = tmem + 320 + s * 8;
                    const uint32_t pal = tmem + 384 + s * 8;
                    mma_f16_ts_cg1(tmem + 256, pah, dVh + vb, IDESC_PV, (t > 0 || s > 0));
                    mma_f16_ts_cg1(tmem + 256, pah, dVl + vb, IDESC_PV, 1);
                    mma_f16_ts_cg1(tmem + 256, pal, dVh + vb, IDESC_PV, 1);
                }
                TCGEN05_COMMIT(mbarO);
            }
        }
    }

    // merge l quarters
    *reinterpret_cast<float*>(smem + AT_LPART + (qrow * 4 + quarter) * 4) = l_part;
    __syncthreads();

    MBARRIER_WAIT_PARITY(mbarO, 1);
    TCGEN05_FENCE_AFTER();

    // epilogue: warps with quarter<2 write O cols [quarter*32, +32)
    if (quarter < 2) {
        const float* lp4 = reinterpret_cast<const float*>(smem + AT_LPART) + qrow * 4;
        const float lsum = lp4[0] + lp4[1] + lp4[2] + lp4[3];
        const float inv = 1.0f / lsum;
        uint32_t o0[32];
        TCGEN05_LD_32X32B_X32(o0, tmem + 256 + quarter * 32 + loff);
        TCGEN05_WAIT_LD();
        uint32_t hibuf[16], lobuf[16];
#pragma unroll
        for (int c = 0; c < 16; c++) {
            float f0 = __uint_as_float(o0[2*c])     * inv;
            float f1 = __uint_as_float(o0[2*c + 1]) * inv;
            uint32_t wh;
            asm("cvt.rn.bf16x2.f32 %0, %1, %2;" : "=r"(wh) : "f"(f1), "f"(f0));
            float h0 = __uint_as_float(wh << 16);
            float h1 = __uint_as_float(wh & 0xffff0000u);
            float q0 = f0 - h0, q1 = f1 - h1;
            uint32_t wl;
            asm("cvt.rn.bf16x2.f32 %0, %1, %2;" : "=r"(wl) : "f"(q1), "f"(q0));
            hibuf[c] = wh; lobuf[c] = wl;
        }
        const size_t rowoff = (((size_t)(tok0 + qrow)) << 10) + colb + quarter * 32;
#pragma unroll
        for (int v4 = 0; v4 < 4; v4++) {
            *reinterpret_cast<uint4*>(Ohi_g + rowoff + v4 * 8) =
                *reinterpret_cast<uint4*>(&hibuf[v4 * 4]);
            *reinterpret_cast<uint4*>(Olo_g + rowoff + v4 * 8) =
                *reinterpret_cast<uint4*>(&lobuf[v4 * 4]);
        }
    }
    __syncthreads();
    if (wid == 0) {
        TCGEN05_RELINQUISH();
        TCGEN05_DEALLOC(tmem, 512);
    }
#endif
}

// ---------------- fp32 -> bf16 hi/lo split ----------------------------------
__global__ __launch_bounds__(256)
void split_bf16_kernel(const float4* __restrict__ in,
                       uint2* __restrict__ hi, uint2* __restrict__ lo, int n4)
{
    const int i = blockIdx.x * blockDim.x + threadIdx.x;
    if (i >= n4) return;
    float4 v = in[i];
    __nv_bfloat16 h0 = __float2bfloat16_rn(v.x);
    __nv_bfloat16 h1 = __float2bfloat16_rn(v.y);
    __nv_bfloat16 h2 = __float2bfloat16_rn(v.z);
    __nv_bfloat16 h3 = __float2bfloat16_rn(v.w);
    __nv_bfloat16 l0 = __float2bfloat16_rn(v.x - __bfloat162float(h0));
    __nv_bfloat16 l1 = __float2bfloat16_rn(v.y - __bfloat162float(h1));
    __nv_bfloat16 l2 = __float2bfloat16_rn(v.z - __bfloat162float(h2));
    __nv_bfloat16 l3 = __float2bfloat16_rn(v.w - __bfloat162float(h3));
    uint2 ph, pl;
    ph.x = ((uint32_t)__bfloat16_as_ushort(h1) << 16) | __bfloat16_as_ushort(h0);
    ph.y = ((uint32_t)__bfloat16_as_ushort(h3) << 16) | __bfloat16_as_ushort(h2);
    pl.x = ((uint32_t)__bfloat16_as_ushort(l1) << 16) | __bfloat16_as_ushort(l0);
    pl.y = ((uint32_t)__bfloat16_as_ushort(l3) << 16) | __bfloat16_as_ushort(l2);
    hi[i] = ph;
    lo[i] = pl;
}

// ---------------- W [K,N] -> W^T hi/lo bf16 [N,K], all 4 weights ------------
__global__ __launch_bounds__(256)
void transpose_split4_kernel(const float* __restrict__ W0,
                             const float* __restrict__ W1,
                             const float* __restrict__ W2,
                             const float* __restrict__ W3,
                             __nv_bfloat16* __restrict__ Thi,
                             __nv_bfloat16* __restrict__ Tlo)
{
    __shared__ float tile[32][33];
    const int w = blockIdx.z;
    const float* W = (w == 0) ? W0 : (w == 1) ? W1 : (w == 2) ? W2 : W3;
    __nv_bfloat16* thi = Thi + (size_t)w * EDIM * EDIM;
    __nv_bfloat16* tlo = Tlo + (size_t)w * EDIM * EDIM;
    const int bx = blockIdx.x * 32;
    const int by = blockIdx.y * 32;
    const int tx = threadIdx.x & 31, ty = threadIdx.x >> 5;
#pragma unroll
    for (int j = ty; j < 32; j += 8)
        tile[j][tx] = W[(size_t)(by + j) * EDIM + bx + tx];
    __syncthreads();
#pragma unroll
    for (int j = ty; j < 32; j += 8) {
        float v = tile[tx][j];
        __nv_bfloat16 h = __float2bfloat16_rn(v);
        __nv_bfloat16 l = __float2bfloat16_rn(v - __bfloat162float(h));
        thi[(size_t)(bx + j) * EDIM + by + tx] = h;
        tlo[(size_t)(bx + j) * EDIM + by + tx] = l;
    }
}

// ---------------- cumprod(cos(x)) -> bf16 hi/lo, warp-per-row, z picks q/k --
__global__ __launch_bounds__(256)
void cumprod_cos_split_kernel(const float* __restrict__ in0,
                              __nv_bfloat16* __restrict__ hi0,
                              __nv_bfloat16* __restrict__ lo0,
                              const float* __restrict__ in1,
                              __nv_bfloat16* __restrict__ hi1,
                              __nv_bfloat16* __restrict__ lo1)
{
    const float* in = blockIdx.z ? in1 : in0;
    __nv_bfloat16* hi = blockIdx.z ? hi1 : hi0;
    __nv_bfloat16* lo = blockIdx.z ? lo1 : lo0;
    const int row  = blockIdx.x * 8 + (threadIdx.x >> 5);
    const int lane = threadIdx.x & 31;
    const float* rp = in + (size_t)row * EDIM + lane * 32;

    float v[32];
#pragma unroll
    for (int i = 0; i < 8; i++) {
        float4 f = reinterpret_cast<const float4*>(rp)[i];
        v[4*i+0] = f.x; v[4*i+1] = f.y; v[4*i+2] = f.z; v[4*i+3] = f.w;
    }
    float c = 1.0f;
#pragma unroll
    for (int i = 0; i < 32; i++) { c *= __cosf(v[i]); v[i] = c; }
    float p = c;
#pragma unroll
    for (int off = 1; off < 32; off <<= 1) {
        float t = __shfl_up_sync(0xffffffffu, p, off);
        if (lane >= off) p *= t;
    }
    float excl = __shfl_up_sync(0xffffffffu, p, 1);
    if (lane == 0) excl = 1.0f;

    uint32_t hiw[16], low[16];
#pragma unroll
    for (int j = 0; j < 16; j++) {
        float f0 = v[2*j] * excl;
        float f1 = v[2*j + 1] * excl;
        uint32_t wh;
        asm("cvt.rn.bf16x2.f32 %0, %1, %2;" : "=r"(wh) : "f"(f1), "f"(f0));
        float h0 = __uint_as_float(wh << 16);
        float h1 = __uint_as_float(wh & 0xffff0000u);
        float q0 = f0 - h0, q1 = f1 - h1;
        uint32_t wl;
        asm("cvt.rn.bf16x2.f32 %0, %1, %2;" : "=r"(wl) : "f"(q1), "f"(q0));
        hiw[j] = wh; low[j] = wl;
    }
    __nv_bfloat16* hp = hi + (size_t)row * EDIM + lane * 32;
    __nv_bfloat16* lp = lo + (size_t)row * EDIM + lane * 32;
#pragma unroll
    for (int j4 = 0; j4 < 4; j4++) {
        *reinterpret_cast<uint4*>(hp + j4 * 8) = *reinterpret_cast<uint4*>(&hiw[j4 * 4]);
        *reinterpret_cast<uint4*>(lp + j4 * 8) = *reinterpret_cast<uint4*>(&low[j4 * 4]);
    }
}

// ---------------- launch ----------------------------------------------------
extern "C" void kernel_launch(void* const* d_in, const int* in_sizes, int n_in,
                              void* d_out, int out_size)
{
    const float* x  = (const float*)d_in[0];
    const float* Wq = (const float*)d_in[1];
    const float* bq = (const float*)d_in[2];
    const float* Wk = (const float*)d_in[3];
    const float* bk = (const float*)d_in[4];
    const float* Wv = (const float*)d_in[5];
    const float* bv = (const float*)d_in[6];
    const float* Wo = (const float*)d_in[7];
    const float* bo = (const float*)d_in[8];
    float* out = (float*)d_out;

    float *q, *k;
    __nv_bfloat16 *xhi, *xlo, *qhi, *qlo, *khi, *klo, *vthi, *vtlo, *aohi, *aolo, *wthi, *wtlo;
    cudaGetSymbolAddress((void**)&q,    g_q);
    cudaGetSymbolAddress((void**)&k,    g_k);
    cudaGetSymbolAddress((void**)&xhi,  g_xhi);
    cudaGetSymbolAddress((void**)&xlo,  g_xlo);
    cudaGetSymbolAddress((void**)&qhi,  g_qhi);
    cudaGetSymbolAddress((void**)&qlo,  g_qlo);
    cudaGetSymbolAddress((void**)&khi,  g_khi);
    cudaGetSymbolAddress((void**)&klo,  g_klo);
    cudaGetSymbolAddress((void**)&vthi, g_vthi);
    cudaGetSymbolAddress((void**)&vtlo, g_vtlo);
    cudaGetSymbolAddress((void**)&aohi, g_aohi);
    cudaGetSymbolAddress((void**)&aolo, g_aolo);
    cudaGetSymbolAddress((void**)&wthi, g_wthi);
    cudaGetSymbolAddress((void**)&wtlo, g_wtlo);

    cudaFuncSetAttribute(gemm_tc2_kernel, cudaFuncAttributeMaxDynamicSharedMemorySize, GEMM_SMEM);
    cudaFuncSetAttribute(attention_tc_kernel, cudaFuncAttributeMaxDynamicSharedMemorySize, AT_SMEM_TOTAL);

    const int n4 = MROWS * EDIM / 4;
    split_bf16_kernel<<<(n4 + 255) / 256, 256>>>((const float4*)x, (uint2*)xhi, (uint2*)xlo, n4);

    dim3 tg4(32, 32, 4);
    transpose_split4_kernel<<<tg4, 256>>>(Wq, Wk, Wv, Wo, wthi, wtlo);

    dim3 gqkv(EDIM / 256, MROWS / 128, 3);
    gemm_tc2_kernel<<<gqkv, 512, GEMM_SMEM>>>(xhi, xlo, wthi, wtlo, 0,
                                              bq, bk, bv, q, k, vthi, vtlo, 2);

    dim3 gc(MROWS / 8, 1, 2);
    cumprod_cos_split_kernel<<<gc, 256>>>(q, qhi, qlo, k, khi, klo);

    // role swap: attention-Q = quantum(k-proj), attention-K = quantum(q-proj)
    dim3 ga(TQ / 128, NH, NB);
    attention_tc_kernel<<<ga, AT_THREADS, AT_SMEM_TOTAL>>>(khi, klo, qhi, qlo, vthi, vtlo, aohi, aolo);

    dim3 go(EDIM / 256, MROWS / 128, 1);
    gemm_tc2_kernel<<<go, 512, GEMM_SMEM>>>(aohi, aolo, wthi, wtlo, 3,
                                            bo, bo, bo, out, out, nullptr, nullptr, -1);
}